// round 1
// baseline (speedup 1.0000x reference)
#include <cuda_runtime.h>
#include <math_constants.h>
#include <cstdint>

// DetectPeaksTM: per-row sliding max (K=301) NMS + top-2 (value, index).
// Input : xcorr [32,3,64,8192] fp32  -> 6144 rows of 8192
// Output: concat(topk_score [6144,2], topk_idx [6144,2]) as float32
//
// Algorithm per row (one CTA, 256 threads):
//   xp = [-inf pad(160) | abs(x) (8192) | -inf pad] in smem
//   Tile size 301 == window size. P = per-tile prefix max, S = per-tile suffix max.
//   winmax(i) = max(S[i+10], P[i+310])   (exact, incl. tile-aligned case)
//   score(i)  = (xp[i+160] == winmax(i)) ? xp[i+160] : 0
//   top-2 of score with tie-break: equal value -> lower index (matches lax.top_k)

#define NT      8192
#define HALF    150
#define TILE    301
#define NTILES  29          // ceil(8729/301); covers all P/S indices we read
#define PAD     160         // left pad, float4-aligned
#define ARR     8752        // >= 28*301 + 319 (chunk over-read), 16B multiple

__device__ __forceinline__ bool better(float av, int ai, float bv, int bi) {
    return (av > bv) || (av == bv && ai < bi);
}

__device__ __forceinline__ void merge2(float& a1, int& x1, float& a2, int& x2,
                                       float b1, int y1, float b2, int y2) {
    if (better(b1, y1, a1, x1)) {
        // b1 is new best
        float na2; int nx2;
        if (better(a1, x1, b2, y2)) { na2 = a1; nx2 = x1; } else { na2 = b2; nx2 = y2; }
        a1 = b1; x1 = y1; a2 = na2; x2 = nx2;
    } else {
        if (better(b1, y1, a2, x2)) { a2 = b1; x2 = y1; }
    }
}

__global__ void __launch_bounds__(256)
detect_peaks_kernel(const float* __restrict__ x, float* __restrict__ out, int nrows) {
    extern __shared__ float sm[];
    float* xp = sm;             // [ARR]
    float* P  = sm + ARR;       // [ARR]
    float* S  = sm + 2 * ARR;   // [ARR]

    const int row  = blockIdx.x;
    const int tid  = threadIdx.x;
    const int lane = tid & 31;
    const int warp = tid >> 5;
    const unsigned FULL = 0xffffffffu;

    // --- init pads with -inf ---
    for (int j = tid; j < PAD; j += 256) xp[j] = -CUDART_INF_F;
    for (int j = PAD + NT + tid; j < ARR; j += 256) xp[j] = -CUDART_INF_F;

    // --- load row, abs, store to smem (float4, aligned: PAD=160) ---
    const float4* src = (const float4*)(x + (size_t)row * NT);
    float4* dst = (float4*)(xp + PAD);
#pragma unroll
    for (int k = 0; k < NT / 4 / 256; k++) {   // 8 iters
        float4 v = src[tid + 256 * k];
        v.x = fabsf(v.x); v.y = fabsf(v.y); v.z = fabsf(v.z); v.w = fabsf(v.w);
        dst[tid + 256 * k] = v;
    }
    __syncthreads();

    // --- per-tile prefix (P) and suffix (S) max scans; one warp per tile ---
    for (int t = warp; t < NTILES; t += 8) {
        const int base = t * TILE;
        // prefix max
        float carry = -CUDART_INF_F;
#pragma unroll
        for (int c = 0; c < 10; c++) {
            int off = c * 32 + lane;
            float v = xp[base + off];
#pragma unroll
            for (int d = 1; d < 32; d <<= 1) {
                float o = __shfl_up_sync(FULL, v, d);
                if (lane >= d) v = fmaxf(v, o);
            }
            v = fmaxf(v, carry);
            if (off <= 300) P[base + off] = v;
            carry = __shfl_sync(FULL, v, 31);
        }
        // suffix max
        carry = -CUDART_INF_F;
#pragma unroll
        for (int c = 9; c >= 0; c--) {
            int off = c * 32 + lane;
            float v = (off <= 300) ? xp[base + off] : -CUDART_INF_F;
#pragma unroll
            for (int d = 1; d < 32; d <<= 1) {
                float o = __shfl_down_sync(FULL, v, d);
                if (lane + d < 32) v = fmaxf(v, o);
            }
            v = fmaxf(v, carry);
            if (off <= 300) S[base + off] = v;
            carry = __shfl_sync(FULL, v, 0);
        }
    }
    __syncthreads();

    // --- evaluate scores, keep per-thread top-2 ---
    float v1 = -CUDART_INF_F, v2 = -CUDART_INF_F;
    int   i1 = 0x7fffffff,     i2 = 0x7fffffff;
#pragma unroll
    for (int k = 0; k < NT / 256; k++) {       // 32 iters
        int i = tid + (k << 8);
        float val = xp[i + PAD];
        float m = fmaxf(S[i + (PAD - HALF)], P[i + (PAD + HALF)]);
        float s = (val == m) ? val : 0.0f;
        if (better(s, i, v2, i2)) {
            if (better(s, i, v1, i1)) { v2 = v1; i2 = i1; v1 = s; i1 = i; }
            else                      { v2 = s;  i2 = i; }
        }
    }

    // --- warp reduction of top-2 pairs ---
#pragma unroll
    for (int d = 16; d > 0; d >>= 1) {
        float ov1 = __shfl_down_sync(FULL, v1, d);
        int   oi1 = __shfl_down_sync(FULL, i1, d);
        float ov2 = __shfl_down_sync(FULL, v2, d);
        int   oi2 = __shfl_down_sync(FULL, i2, d);
        merge2(v1, i1, v2, i2, ov1, oi1, ov2, oi2);
    }

    __shared__ float wv1[8], wv2[8];
    __shared__ int   wi1[8], wi2[8];
    if (lane == 0) { wv1[warp] = v1; wi1[warp] = i1; wv2[warp] = v2; wi2[warp] = i2; }
    __syncthreads();

    if (tid == 0) {
        float a1 = wv1[0], a2 = wv2[0];
        int   b1 = wi1[0], b2 = wi2[0];
#pragma unroll
        for (int w = 1; w < 8; w++)
            merge2(a1, b1, a2, b2, wv1[w], wi1[w], wv2[w], wi2[w]);
        // scores first, then indices (as float), matching flattened tuple concat
        out[row * 2 + 0] = a1;
        out[row * 2 + 1] = a2;
        out[(size_t)nrows * 2 + row * 2 + 0] = (float)b1;
        out[(size_t)nrows * 2 + row * 2 + 1] = (float)b2;
    }
}

extern "C" void kernel_launch(void* const* d_in, const int* in_sizes, int n_in,
                              void* d_out, int out_size) {
    const float* x = (const float*)d_in[0];
    float* out = (float*)d_out;
    int nrows = in_sizes[0] / NT;   // 6144

    size_t smem = (size_t)3 * ARR * sizeof(float);  // 105024 B
    cudaFuncSetAttribute(detect_peaks_kernel,
                         cudaFuncAttributeMaxDynamicSharedMemorySize, (int)smem);

    detect_peaks_kernel<<<nrows, 256, smem>>>(x, out, nrows);
}

// round 2
// speedup vs baseline: 1.3133x; 1.3133x over previous
#include <cuda_runtime.h>
#include <math_constants.h>
#include <cstdint>

// DetectPeaksTM: per-row sliding max (K=301) NMS + top-2 (value, index).
// Input : xcorr [32,3,64,8192] fp32  -> 6144 rows of 8192
// Output: concat(topk_score [6144,2], topk_idx [6144,2]) as float32
//
// One CTA (512 threads) per row. Van Herk two-scan with tile size 301:
//   winmax(i) = max(S[i+10], P[i+310])   (padded coords, PAD=160)
// Scans use a 3-phase register-segmented approach: each lane holds 10
// contiguous elements in registers, one shfl-scan of lane totals per tile
// per direction.

#define NT      8192
#define HALF    150
#define TILE    301
#define NTILES  29
#define PAD     160
#define ARR     8752        // holds up to index 8747 read by last tile's lanes
#define SEG     10          // elements per lane in scan phase (32*10=320>=301)

__device__ __forceinline__ bool better(float av, int ai, float bv, int bi) {
    return (av > bv) || (av == bv && ai < bi);
}

__device__ __forceinline__ void merge2(float& a1, int& x1, float& a2, int& x2,
                                       float b1, int y1, float b2, int y2) {
    if (better(b1, y1, a1, x1)) {
        float na2; int nx2;
        if (better(a1, x1, b2, y2)) { na2 = a1; nx2 = x1; } else { na2 = b2; nx2 = y2; }
        a1 = b1; x1 = y1; a2 = na2; x2 = nx2;
    } else {
        if (better(b1, y1, a2, x2)) { a2 = b1; x2 = y1; }
    }
}

__global__ void __launch_bounds__(512)
detect_peaks_kernel(const float* __restrict__ x, float* __restrict__ out, int nrows) {
    extern __shared__ float sm[];
    float* xp = sm;             // [ARR]
    float* P  = sm + ARR;       // [ARR]
    float* S  = sm + 2 * ARR;   // [ARR]

    const int row  = blockIdx.x;
    const int tid  = threadIdx.x;
    const int lane = tid & 31;
    const int warp = tid >> 5;
    const unsigned FULL = 0xffffffffu;

    // --- pads ---
    for (int j = tid; j < PAD; j += 512) xp[j] = -CUDART_INF_F;
    for (int j = PAD + NT + tid; j < ARR; j += 512) xp[j] = -CUDART_INF_F;

    // --- load row, abs -> smem (float4; PAD=160 keeps 16B alignment) ---
    const float4* src = (const float4*)(x + (size_t)row * NT);
    float4* dst = (float4*)(xp + PAD);
#pragma unroll
    for (int k = 0; k < NT / 4 / 512; k++) {   // 4 iters
        float4 v = src[tid + 512 * k];
        v.x = fabsf(v.x); v.y = fabsf(v.y); v.z = fabsf(v.z); v.w = fabsf(v.w);
        dst[tid + 512 * k] = v;
    }
    __syncthreads();

    // --- per-tile prefix (P) / suffix (S) scans; one warp per tile ---
    // 29 tiles over 16 warps: warps 0..12 take two tiles.
#pragma unroll
    for (int rep = 0; rep < 2; rep++) {
        int t = warp + rep * 16;
        if (t < NTILES) {
            const int base = t * TILE;
            const int off0 = lane * SEG;

            // load 10 contiguous elements into registers
            float v[SEG];
#pragma unroll
            for (int j = 0; j < SEG; j++) v[j] = xp[base + off0 + j];

            // ---- prefix ----
            float p[SEG];
            p[0] = v[0];
#pragma unroll
            for (int j = 1; j < SEG; j++) p[j] = fmaxf(p[j - 1], v[j]);
            // inclusive scan of lane totals
            float tot = p[SEG - 1];
#pragma unroll
            for (int d = 1; d < 32; d <<= 1) {
                float o = __shfl_up_sync(FULL, tot, d);
                if (lane >= d) tot = fmaxf(tot, o);
            }
            float excl = __shfl_up_sync(FULL, tot, 1);
            if (lane == 0) excl = -CUDART_INF_F;
#pragma unroll
            for (int j = 0; j < SEG; j++) {
                int off = off0 + j;
                if (off <= 300) P[base + off] = fmaxf(excl, p[j]);
            }

            // ---- suffix (mask out-of-tile elements) ----
            float s[SEG];
            {
                int off = off0 + SEG - 1;
                s[SEG - 1] = (off <= 300) ? v[SEG - 1] : -CUDART_INF_F;
            }
#pragma unroll
            for (int j = SEG - 2; j >= 0; j--) {
                int off = off0 + j;
                float w = (off <= 300) ? v[j] : -CUDART_INF_F;
                s[j] = fmaxf(w, s[j + 1]);
            }
            float stot = s[0];
#pragma unroll
            for (int d = 1; d < 32; d <<= 1) {
                float o = __shfl_down_sync(FULL, stot, d);
                if (lane + d < 32) stot = fmaxf(stot, o);
            }
            float sexcl = __shfl_down_sync(FULL, stot, 1);
            if (lane == 31) sexcl = -CUDART_INF_F;
#pragma unroll
            for (int j = 0; j < SEG; j++) {
                int off = off0 + j;
                if (off <= 300) S[base + off] = fmaxf(sexcl, s[j]);
            }
        }
    }
    __syncthreads();

    // --- evaluate scores, per-thread top-2 (indices ascending per thread) ---
    float v1 = -CUDART_INF_F, v2 = -CUDART_INF_F;
    int   i1 = 0x7fffffff,     i2 = 0x7fffffff;
#pragma unroll
    for (int k = 0; k < NT / 512; k++) {       // 16 iters
        int i = tid + (k << 9);
        float val = xp[i + PAD];
        float m = fmaxf(S[i + (PAD - HALF)], P[i + (PAD + HALF)]);
        float sc = (val == m) ? val : 0.0f;
        if (sc > v1)      { v2 = v1; i2 = i1; v1 = sc; i1 = i; }
        else if (sc > v2) { v2 = sc; i2 = i; }
    }

    // --- warp reduction ---
#pragma unroll
    for (int d = 16; d > 0; d >>= 1) {
        float ov1 = __shfl_down_sync(FULL, v1, d);
        int   oi1 = __shfl_down_sync(FULL, i1, d);
        float ov2 = __shfl_down_sync(FULL, v2, d);
        int   oi2 = __shfl_down_sync(FULL, i2, d);
        merge2(v1, i1, v2, i2, ov1, oi1, ov2, oi2);
    }

    __shared__ float wv1[16], wv2[16];
    __shared__ int   wi1[16], wi2[16];
    if (lane == 0) { wv1[warp] = v1; wi1[warp] = i1; wv2[warp] = v2; wi2[warp] = i2; }
    __syncthreads();

    if (tid == 0) {
        float a1 = wv1[0], a2 = wv2[0];
        int   b1 = wi1[0], b2 = wi2[0];
#pragma unroll
        for (int w = 1; w < 16; w++)
            merge2(a1, b1, a2, b2, wv1[w], wi1[w], wv2[w], wi2[w]);
        out[row * 2 + 0] = a1;
        out[row * 2 + 1] = a2;
        out[(size_t)nrows * 2 + row * 2 + 0] = (float)b1;
        out[(size_t)nrows * 2 + row * 2 + 1] = (float)b2;
    }
}

extern "C" void kernel_launch(void* const* d_in, const int* in_sizes, int n_in,
                              void* d_out, int out_size) {
    const float* x = (const float*)d_in[0];
    float* out = (float*)d_out;
    int nrows = in_sizes[0] / NT;   // 6144

    size_t smem = (size_t)3 * ARR * sizeof(float);  // 105024 B
    cudaFuncSetAttribute(detect_peaks_kernel,
                         cudaFuncAttributeMaxDynamicSharedMemorySize, (int)smem);

    detect_peaks_kernel<<<nrows, 512, smem>>>(x, out, nrows);
}

// round 3
// speedup vs baseline: 1.8181x; 1.3844x over previous
#include <cuda_runtime.h>
#include <math_constants.h>
#include <cstdint>

// DetectPeaksTM: per-row sliding max (K=301) NMS + top-2 (value, index).
// Candidate-based: survivors must be the max of their aligned 128-tile.
// Per-tile top-2 candidates computed in registers during the load; then
// warp 0 selects best candidates in (val desc, idx asc) order and verifies
// each against the 301-wide window max in smem until 2 survivors found.

#define NT    8192
#define HALF  150
#define WIN   301

typedef unsigned long long u64;

__device__ __forceinline__ u64 umax64(u64 a, u64 b) { return a > b ? a : b; }
__device__ __forceinline__ u64 umin64(u64 a, u64 b) { return a < b ? a : b; }

// key = (float bits << 32) | ~idx  -> max key == (largest val, lowest idx)
__device__ __forceinline__ u64 packkey(float v, int idx) {
    return ((u64)__float_as_uint(v) << 32) | (unsigned)(~idx);
}

__device__ __forceinline__ u64 shfl_xor_u64(u64 v, int d) {
    unsigned lo = (unsigned)v, hi = (unsigned)(v >> 32);
    lo = __shfl_xor_sync(0xffffffffu, lo, d);
    hi = __shfl_xor_sync(0xffffffffu, hi, d);
    return ((u64)hi << 32) | lo;
}

__global__ void __launch_bounds__(512)
detect_peaks_kernel(const float* __restrict__ x, float* __restrict__ out, int nrows) {
    __shared__ float xp[NT];          // 32 KB
    __shared__ u64   cand[128];       // 64 tiles x top-2

    const int row  = blockIdx.x;
    const int tid  = threadIdx.x;
    const int lane = tid & 31;
    const int warp = tid >> 5;

    const float4* src = (const float4*)(x + (size_t)row * NT);
    float4* dst = (float4*)xp;

    // ---- load + abs + per-tile (128 floats == one warp-iteration) top-2 ----
#pragma unroll
    for (int k = 0; k < 4; k++) {
        int f = tid + 512 * k;                 // float4 index
        float4 v = src[f];
        v.x = fabsf(v.x); v.y = fabsf(v.y); v.z = fabsf(v.z); v.w = fabsf(v.w);
        dst[f] = v;

        int e = f << 2;                        // element index of v.x
        // thread-local top-2 (keys are unique: idx distinct)
        u64 a = packkey(v.x, e);
        u64 b = packkey(v.y, e + 1);
        u64 c = packkey(v.z, e + 2);
        u64 d = packkey(v.w, e + 3);
        u64 k1 = umax64(a, b), k2 = umin64(a, b);
        k2 = umax64(k2, umin64(k1, c)); k1 = umax64(k1, c);
        k2 = umax64(k2, umin64(k1, d)); k1 = umax64(k1, d);

        // warp butterfly top-2 reduce
#pragma unroll
        for (int s = 16; s > 0; s >>= 1) {
            u64 o1 = shfl_xor_u64(k1, s);
            u64 o2 = shfl_xor_u64(k2, s);
            k2 = umax64(umax64(k2, o2), umin64(k1, o1));
            k1 = umax64(k1, o1);
        }

        int tile = warp + 16 * k;              // 0..63
        if (lane == 0) { cand[2 * tile] = k1; cand[2 * tile + 1] = k2; }
    }
    __syncthreads();

    // ---- selection + verification (warp 0 only) ----
    if (warp == 0) {
        u64 c0 = cand[lane], c1 = cand[lane + 32];
        u64 c2 = cand[lane + 64], c3 = cand[lane + 96];

        float rv0 = 0.0f, rv1 = 0.0f;
        int   ri0 = 0,    ri1 = 0;
        int found = 0;

        for (int it = 0; it < 128; it++) {
            // global best unconsumed candidate
            u64 best = umax64(umax64(c0, c1), umax64(c2, c3));
#pragma unroll
            for (int s = 16; s > 0; s >>= 1)
                best = umax64(best, shfl_xor_u64(best, s));
            if (best == 0ull) break;

            // consume it (keys unique -> exactly one match)
            if (c0 == best) c0 = 0;
            if (c1 == best) c1 = 0;
            if (c2 == best) c2 = 0;
            if (c3 == best) c3 = 0;

            int   idx = (int)(~(unsigned)best & 0xffffffffu);
            idx = ~(int)(unsigned)best;               // recover idx
            idx = (int)(~(unsigned)(best & 0xffffffffull));
            float val = __uint_as_float((unsigned)(best >> 32));

            // verify: window max over [idx-150, idx+150] (clamped reads stay
            // inside the window when out of range on that side)
            float m = -CUDART_INF_F;
            int lo = idx - HALF;
#pragma unroll
            for (int r = 0; r < 10; r++) {
                int off = lane + 32 * r;
                int p = lo + off;
                p = min(max(p, 0), NT - 1);
                float xv = xp[p];
                if (off < WIN) m = fmaxf(m, xv);
            }
#pragma unroll
            for (int s = 16; s > 0; s >>= 1)
                m = fmaxf(m, __shfl_xor_sync(0xffffffffu, m, s));

            if (m <= val) {                    // survivor
                if (found == 0) { rv0 = val; ri0 = idx; }
                else            { rv1 = val; ri1 = idx; }
                found++;
                if (found == 2) break;
            }
        }

        if (lane == 0) {
            if (found < 2) {                   // <2 survivors: next score is 0
                rv1 = 0.0f;
                ri1 = (found >= 1 && ri0 == 0) ? 1 : 0;
            }
            out[row * 2 + 0] = rv0;
            out[row * 2 + 1] = rv1;
            out[(size_t)nrows * 2 + row * 2 + 0] = (float)ri0;
            out[(size_t)nrows * 2 + row * 2 + 1] = (float)ri1;
        }
    }
}

extern "C" void kernel_launch(void* const* d_in, const int* in_sizes, int n_in,
                              void* d_out, int out_size) {
    const float* x = (const float*)d_in[0];
    float* out = (float*)d_out;
    int nrows = in_sizes[0] / NT;   // 6144
    detect_peaks_kernel<<<nrows, 512>>>(x, out, nrows);
}

// round 4
// speedup vs baseline: 4.4687x; 2.4578x over previous
#include <cuda_runtime.h>
#include <math_constants.h>
#include <cstdint>

// DetectPeaksTM: per-row sliding max (K=301) NMS + top-2 (value, index).
// Candidate-based, values-only hot loop:
//   - survivors must equal the max of their aligned 128-tile (128 <= 151)
//   - per-tile top-2 VALUES via u32 IMNMX + REDUX.SYNC (no indices, no u64)
//   - warp 0 selects candidates best-first, recovers index by rescanning the
//     tile, verifies against the 301-wide window max from gmem (L2-hot).

#define NT    8192
#define HALF  150
#define WIN   301

typedef unsigned long long u64;
typedef unsigned int u32;

__device__ __forceinline__ u64 umax64(u64 a, u64 b) { return a > b ? a : b; }

__device__ __forceinline__ u64 shfl_xor_u64(u64 v, int d) {
    u32 lo = (u32)v, hi = (u32)(v >> 32);
    lo = __shfl_xor_sync(0xffffffffu, lo, d);
    hi = __shfl_xor_sync(0xffffffffu, hi, d);
    return ((u64)hi << 32) | lo;
}

__global__ void __launch_bounds__(512)
detect_peaks_kernel(const float* __restrict__ x, float* __restrict__ out, int nrows) {
    __shared__ u32 cand[128];     // 64 tiles x {m1, m2} abs-value bits

    const int row  = blockIdx.x;
    const int tid  = threadIdx.x;
    const int lane = tid & 31;
    const int warp = tid >> 5;
    const u32 FULL = 0xffffffffu;

    const float* xr = x + (size_t)row * NT;
    const float4* src = (const float4*)xr;

    // ---- hot loop: per-128-tile top-2 abs values (u32 domain) ----
    float4 v[4];
#pragma unroll
    for (int k = 0; k < 4; k++) v[k] = src[tid + 512 * k];

#pragma unroll
    for (int k = 0; k < 4; k++) {
        u32 a = __float_as_uint(v[k].x) & 0x7fffffffu;
        u32 b = __float_as_uint(v[k].y) & 0x7fffffffu;
        u32 c = __float_as_uint(v[k].z) & 0x7fffffffu;
        u32 d = __float_as_uint(v[k].w) & 0x7fffffffu;
        u32 l1 = max(a, b), l2 = min(a, b), t;
        t = min(l1, c); l1 = max(l1, c); l2 = max(l2, t);
        t = min(l1, d); l1 = max(l1, d); l2 = max(l2, t);

        u32 m1 = __reduce_max_sync(FULL, l1);
        u32 bal = __ballot_sync(FULL, l1 == m1);
        u32 contrib = (l1 == m1) ? l2 : l1;      // local dup of m1 -> l2==m1, still correct
        u32 m2r = __reduce_max_sync(FULL, contrib);
        u32 m2 = (__popc(bal) > 1) ? m1 : m2r;

        int tile = warp + 16 * k;                // 0..63
        if (lane == 0) { cand[2 * tile] = m1; cand[2 * tile + 1] = m2; }
    }
    __syncthreads();

    // ---- selection + verification (warp 0; rare path) ----
    if (warp == 0) {
        // slot s = tile*2 + inTile; key orders (val desc, slot asc)
        u64 k0 = ((u64)cand[lane]       << 32) | (u32)(127 - lane);
        u64 k1 = ((u64)cand[lane + 32]  << 32) | (u32)(127 - (lane + 32));
        u64 k2 = ((u64)cand[lane + 64]  << 32) | (u32)(127 - (lane + 64));
        u64 k3 = ((u64)cand[lane + 96]  << 32) | (u32)(127 - (lane + 96));

        float rv0 = 0.0f, rv1 = 0.0f;
        int   ri0 = 0,    ri1 = 0;
        int found = 0;

        for (int it = 0; it < 128 && found < 2; it++) {
            u64 best = umax64(umax64(k0, k1), umax64(k2, k3));
#pragma unroll
            for (int s = 16; s > 0; s >>= 1) best = umax64(best, shfl_xor_u64(best, s));
            if (best == 0ull) break;
            if (k0 == best) k0 = 0;
            if (k1 == best) k1 = 0;
            if (k2 == best) k2 = 0;
            if (k3 == best) k3 = 0;

            u32 bits = (u32)(best >> 32);
            int slot = 127 - (int)(best & 0xffffffffull);
            int tile = slot >> 1, inTile = slot & 1;
            // if both slots of this tile carry the same value, slot1 is the
            // 2nd-lowest matching index within the tile
            int occ = (inTile && cand[slot - 1] == bits) ? 1 : 0;

            // recover element index: rescan the tile (coalesced, L2-hot)
            float4 tv = ((const float4*)(xr + tile * 128))[lane];
            u32 mm = 0;
            if ((__float_as_uint(tv.x) & 0x7fffffffu) == bits) mm |= 1u;
            if ((__float_as_uint(tv.y) & 0x7fffffffu) == bits) mm |= 2u;
            if ((__float_as_uint(tv.z) & 0x7fffffffu) == bits) mm |= 4u;
            if ((__float_as_uint(tv.w) & 0x7fffffffu) == bits) mm |= 8u;
            u32 lb = __ballot_sync(FULL, mm != 0);
            int lf = __ffs((int)lb) - 1;
            u32 mf = __shfl_sync(FULL, mm, lf);
            int need = occ, uselane = lf;
            u32 usem = mf;
            if (__popc(mf) <= occ) {             // occ-th match lives in a later lane
                need = occ - __popc(mf);
                u32 lb2 = lb & ~(1u << lf);
                uselane = __ffs((int)lb2) - 1;
                usem = __shfl_sync(FULL, mm, uselane);
            }
            int j = 0;
            for (int q = 0; q < 4; q++) {
                if (usem & (1u << q)) { if (need == 0) { j = q; break; } need--; }
            }
            int idx = tile * 128 + uselane * 4 + j;

            // verify: 301-wide window max (clamped reads stay inside window)
            int lo = idx - HALF;
            u32 mb = 0;
#pragma unroll
            for (int r = 0; r < 10; r++) {
                int off = lane + 32 * r;
                int p = min(max(lo + off, 0), NT - 1);
                u32 xb = __float_as_uint(__ldg(xr + p)) & 0x7fffffffu;
                if (off < WIN) mb = max(mb, xb);
            }
            mb = __reduce_max_sync(FULL, mb);

            if (mb <= bits) {                    // survivor
                if (found == 0) { rv0 = __uint_as_float(bits); ri0 = idx; }
                else            { rv1 = __uint_as_float(bits); ri1 = idx; }
                found++;
            }
        }

        if (lane == 0) {
            if (found < 2) {                     // <2 survivors: next score is 0
                rv1 = 0.0f;
                ri1 = (found >= 1 && ri0 == 0) ? 1 : 0;
            }
            out[row * 2 + 0] = rv0;
            out[row * 2 + 1] = rv1;
            out[(size_t)nrows * 2 + row * 2 + 0] = (float)ri0;
            out[(size_t)nrows * 2 + row * 2 + 1] = (float)ri1;
        }
    }
}

extern "C" void kernel_launch(void* const* d_in, const int* in_sizes, int n_in,
                              void* d_out, int out_size) {
    const float* x = (const float*)d_in[0];
    float* out = (float*)d_out;
    int nrows = in_sizes[0] / NT;   // 6144
    detect_peaks_kernel<<<nrows, 512>>>(x, out, nrows);
}